// round 4
// baseline (speedup 1.0000x reference)
#include <cuda_runtime.h>
#include <math.h>

#define NFEAT 18
#define NTRK  1500
#define BSZ   64
#define NTRACK (BSZ*NTRK)        // 96000
#define LHID  128
#define HID   256
#define TSTEPS 6
#define NT_TILE 16
#define NPAIR   8                // NT_TILE/2 f32x2 pairs
#define CTA_THREADS 128

// output layout offsets (floats)
#define OUT_POS   24576000       // 96000*256
#define OUT_LOGPT 36864000       // + 96000*128
#define OUT_ETA   36960000
#define OUT_PHI   37056000

typedef unsigned long long u64;

// ---------------- device scratch (transposed weights) ----------------
__device__ __align__(16) float g_wt_ih0[2   * 512];   // [k][j*4+g]
__device__ __align__(16) float g_wt_hh0[128 * 512];
__device__ __align__(16) float g_wt_ih1[128 * 512];
__device__ __align__(16) float g_wt_hh1[128 * 512];
__device__ __align__(16) float g_w0t  [131 * 256];    // [k][j*2+gg]
__device__ __align__(16) float g_w1t  [256 * 256];
__device__ __align__(16) float g_b0c  [512];          // [j*4+g] = b_ih+b_hh
__device__ __align__(16) float g_b1c  [512];
__device__ __align__(16) float g_mb0c [256];          // [j*2+gg]
__device__ __align__(16) float g_mb1c [256];
__device__ float g_posmul[64];                        // 2*pi / dim_t[f]

// ---------------- prep: transpose weights into k-major layouts ----------------
__global__ void prep_kernel(const float* __restrict__ W_ih0, const float* __restrict__ W_hh0,
                            const float* __restrict__ b_ih0, const float* __restrict__ b_hh0,
                            const float* __restrict__ W_ih1, const float* __restrict__ W_hh1,
                            const float* __restrict__ b_ih1, const float* __restrict__ b_hh1,
                            const float* __restrict__ mw0,   const float* __restrict__ mb0,
                            const float* __restrict__ mw1,   const float* __restrict__ mb1)
{
    int stride = gridDim.x * blockDim.x;
    int idx0 = blockIdx.x * blockDim.x + threadIdx.x;

    for (int i = idx0; i < 128 * 512; i += stride) {
        int k = i >> 9, r = i & 511, j = r >> 2, g = r & 3;
        int row = g * 128 + j;
        g_wt_hh0[i] = W_hh0[row * 128 + k];
        g_wt_ih1[i] = W_ih1[row * 128 + k];
        g_wt_hh1[i] = W_hh1[row * 128 + k];
    }
    for (int i = idx0; i < 2 * 512; i += stride) {
        int k = i >> 9, r = i & 511, j = r >> 2, g = r & 3;
        g_wt_ih0[i] = W_ih0[(g * 128 + j) * 2 + k];
    }
    for (int i = idx0; i < 131 * 256; i += stride) {
        int k = i >> 8, r = i & 255, j = r >> 1, gg = r & 1;
        g_w0t[i] = mw0[(gg * 128 + j) * 131 + k];
    }
    for (int i = idx0; i < 256 * 256; i += stride) {
        int k = i >> 8, r = i & 255, j = r >> 1, gg = r & 1;
        g_w1t[i] = mw1[(gg * 128 + j) * 256 + k];
    }
    for (int i = idx0; i < 512; i += stride) {
        int j = i >> 2, g = i & 3;
        g_b0c[i] = b_ih0[g * 128 + j] + b_hh0[g * 128 + j];
        g_b1c[i] = b_ih1[g * 128 + j] + b_hh1[g * 128 + j];
    }
    for (int i = idx0; i < 256; i += stride) {
        int j = i >> 1, gg = i & 1;
        g_mb0c[i] = mb0[gg * 128 + j];
        g_mb1c[i] = mb1[gg * 128 + j];
    }
    for (int i = idx0; i < 64; i += stride) {
        float e = (float)(2 * (i >> 1)) * (1.0f / 64.0f);
        g_posmul[i] = 6.283185307179586f / powf(10000.0f, e);
    }
}

// ---------------- f32x2 helpers ----------------
__device__ __forceinline__ u64 pack2(float x) {
    u64 r; asm("mov.b64 %0, {%1, %1};" : "=l"(r) : "f"(x)); return r;
}
__device__ __forceinline__ void unpack2(u64 v, float &lo, float &hi) {
    asm("mov.b64 {%0, %1}, %2;" : "=f"(lo), "=f"(hi) : "l"(v));
}
__device__ __forceinline__ void ffma2(u64 &d, u64 a, u64 b) {
    asm("fma.rn.f32x2 %0, %1, %2, %0;" : "+l"(d) : "l"(a), "l"(b));
}

// ---------------- activations ----------------
__device__ __forceinline__ float sigf(float x) { return 1.0f / (1.0f + __expf(-x)); }
__device__ __forceinline__ float tanh_fast(float x) {
    float ax = fabsf(x);
    float t = __expf(-2.0f * ax);
    float r = (1.0f - t) / (1.0f + t);
    return copysignf(r, x);
}

// ---------------- inner GEMM helpers (packed f32x2) ----------------
// acc[g][q] (pair n=2q,2q+1) += wt[k][4j+g] * hbuf[k][2q..2q+1], k = 0..127
__device__ __forceinline__ void gate_gemm(u64 acc[4][NPAIR],
                                          const float* __restrict__ wt,
                                          const float (&hbuf)[128][20], int j)
{
#pragma unroll 4
    for (int k = 0; k < 128; ++k) {
        float4 w = *reinterpret_cast<const float4*>(wt + k * 512 + 4 * j);
        u64 w0 = pack2(w.x), w1 = pack2(w.y), w2 = pack2(w.z), w3 = pack2(w.w);
#pragma unroll
        for (int q = 0; q < 4; ++q) {
            ulonglong2 hv = *reinterpret_cast<const ulonglong2*>(&hbuf[k][4 * q]);
            ffma2(acc[0][2 * q], w0, hv.x); ffma2(acc[0][2 * q + 1], w0, hv.y);
            ffma2(acc[1][2 * q], w1, hv.x); ffma2(acc[1][2 * q + 1], w1, hv.y);
            ffma2(acc[2][2 * q], w2, hv.x); ffma2(acc[2][2 * q + 1], w2, hv.y);
            ffma2(acc[3][2 * q], w3, hv.x); ffma2(acc[3][2 * q + 1], w3, hv.y);
        }
    }
}

// a0/a1[q] += wt[k][2j+gg] * hbuf[k][pair q], k = 0..127
__device__ __forceinline__ void mlp_gemm(u64 a0[NPAIR], u64 a1[NPAIR],
                                         const float* __restrict__ wt,
                                         const float (&hbuf)[128][20], int j)
{
#pragma unroll 4
    for (int k = 0; k < 128; ++k) {
        float2 w = *reinterpret_cast<const float2*>(wt + k * 256 + 2 * j);
        u64 w0 = pack2(w.x), w1 = pack2(w.y);
#pragma unroll
        for (int q = 0; q < 4; ++q) {
            ulonglong2 hv = *reinterpret_cast<const ulonglong2*>(&hbuf[k][4 * q]);
            ffma2(a0[2 * q], w0, hv.x); ffma2(a0[2 * q + 1], w0, hv.y);
            ffma2(a1[2 * q], w1, hv.x); ffma2(a1[2 * q + 1], w1, hv.y);
        }
    }
}

// ---------------- fused LSTM(2 layers, 6 steps) + MLP ----------------
__global__ void __launch_bounds__(CTA_THREADS, 3)
lstm_mlp_kernel(const float* __restrict__ tf, float* __restrict__ out)
{
    const int j = threadIdx.x;                 // hidden unit 0..127
    const int track0 = blockIdx.x * NT_TILE;

    __shared__ float h0[128][20];              // pad 20: 80B rows (16B multiple)
    __shared__ float h1[128][20];
    __shared__ float m2[128][20];
    __shared__ float xin[12][NT_TILE];         // feature-major: pairs contiguous in n
    __shared__ float f3s[3][NT_TILE];

    for (int i = j; i < 12 * NT_TILE; i += CTA_THREADS) {
        int f = i / NT_TILE, n = i % NT_TILE;
        int gt = track0 + n, b = gt / NTRK, t = gt - b * NTRK;
        xin[f][n] = tf[((size_t)b * NFEAT + 6 + f) * NTRK + t];
    }
    for (int i = j; i < 3 * NT_TILE; i += CTA_THREADS) {
        int f = i / NT_TILE, n = i % NT_TILE;
        int gt = track0 + n, b = gt / NTRK, t = gt - b * NTRK;
        f3s[f][n] = tf[((size_t)b * NFEAT + f) * NTRK + t];
    }

    float c0[NT_TILE], c1[NT_TILE];
#pragma unroll
    for (int n = 0; n < NT_TILE; ++n) { c0[n] = 0.f; c1[n] = 0.f; h0[j][n] = 0.f; h1[j][n] = 0.f; }
    __syncthreads();

    const float4 bias0 = *reinterpret_cast<const float4*>(g_b0c + 4 * j);
    const float4 bias1 = *reinterpret_cast<const float4*>(g_b1c + 4 * j);
    const u64 b0p[4] = { pack2(bias0.x), pack2(bias0.y), pack2(bias0.z), pack2(bias0.w) };
    const u64 b1p[4] = { pack2(bias1.x), pack2(bias1.y), pack2(bias1.z), pack2(bias1.w) };

    for (int t = 0; t < TSTEPS; ++t) {
        // ------- layer 0 -------
        u64 acc[4][NPAIR];
#pragma unroll
        for (int q = 0; q < NPAIR; ++q) {
            acc[0][q] = b0p[0]; acc[1][q] = b0p[1]; acc[2][q] = b0p[2]; acc[3][q] = b0p[3];
        }
#pragma unroll
        for (int k = 0; k < 2; ++k) {          // tiny input GEMM (x dim = 2)
            float4 w = *reinterpret_cast<const float4*>(g_wt_ih0 + k * 512 + 4 * j);
            u64 w0 = pack2(w.x), w1 = pack2(w.y), w2 = pack2(w.z), w3 = pack2(w.w);
#pragma unroll
            for (int q = 0; q < NPAIR; ++q) {
                u64 xv = *reinterpret_cast<const u64*>(&xin[2 * t + k][2 * q]);
                ffma2(acc[0][q], w0, xv);
                ffma2(acc[1][q], w1, xv);
                ffma2(acc[2][q], w2, xv);
                ffma2(acc[3][q], w3, xv);
            }
        }
        gate_gemm(acc, g_wt_hh0, h0, j);

        float hnew[NT_TILE];
#pragma unroll
        for (int q = 0; q < NPAIR; ++q) {
            float iv[2], fv[2], gv[2], ov[2];
            unpack2(acc[0][q], iv[0], iv[1]);
            unpack2(acc[1][q], fv[0], fv[1]);
            unpack2(acc[2][q], gv[0], gv[1]);
            unpack2(acc[3][q], ov[0], ov[1]);
#pragma unroll
            for (int u = 0; u < 2; ++u) {
                int n = 2 * q + u;
                float ii = sigf(iv[u]), ff = sigf(fv[u]);
                float gg = tanh_fast(gv[u]), oo = sigf(ov[u]);
                c0[n] = ff * c0[n] + ii * gg;
                hnew[n] = oo * tanh_fast(c0[n]);
            }
        }
        __syncthreads();
#pragma unroll
        for (int n = 0; n < NT_TILE; ++n) h0[j][n] = hnew[n];
        __syncthreads();

        // ------- layer 1 -------
#pragma unroll
        for (int q = 0; q < NPAIR; ++q) {
            acc[0][q] = b1p[0]; acc[1][q] = b1p[1]; acc[2][q] = b1p[2]; acc[3][q] = b1p[3];
        }
        gate_gemm(acc, g_wt_ih1, h0, j);
        gate_gemm(acc, g_wt_hh1, h1, j);
#pragma unroll
        for (int q = 0; q < NPAIR; ++q) {
            float iv[2], fv[2], gv[2], ov[2];
            unpack2(acc[0][q], iv[0], iv[1]);
            unpack2(acc[1][q], fv[0], fv[1]);
            unpack2(acc[2][q], gv[0], gv[1]);
            unpack2(acc[3][q], ov[0], ov[1]);
#pragma unroll
            for (int u = 0; u < 2; ++u) {
                int n = 2 * q + u;
                float ii = sigf(iv[u]), ff = sigf(fv[u]);
                float gg = tanh_fast(gv[u]), oo = sigf(ov[u]);
                c1[n] = ff * c1[n] + ii * gg;
                hnew[n] = oo * tanh_fast(c1[n]);
            }
        }
        __syncthreads();
#pragma unroll
        for (int n = 0; n < NT_TILE; ++n) h1[j][n] = hnew[n];
        __syncthreads();
    }

    // ------- MLP layer 0: (3 + 128) -> 256, ReLU -------
    u64 a0[NPAIR], a1[NPAIR];
    const float2 mb0 = *reinterpret_cast<const float2*>(g_mb0c + 2 * j);
    {
        u64 m0 = pack2(mb0.x), m1 = pack2(mb0.y);
#pragma unroll
        for (int q = 0; q < NPAIR; ++q) { a0[q] = m0; a1[q] = m1; }
    }
#pragma unroll
    for (int k = 0; k < 3; ++k) {
        float2 w = *reinterpret_cast<const float2*>(g_w0t + k * 256 + 2 * j);
        u64 w0 = pack2(w.x), w1 = pack2(w.y);
#pragma unroll
        for (int q = 0; q < NPAIR; ++q) {
            u64 xv = *reinterpret_cast<const u64*>(&f3s[k][2 * q]);
            ffma2(a0[q], w0, xv);
            ffma2(a1[q], w1, xv);
        }
    }
    mlp_gemm(a0, a1, g_w0t + 3 * 256, h1, j);
    // safe to overwrite h0/m2: all h0 reads finished before the last barrier
#pragma unroll
    for (int q = 0; q < NPAIR; ++q) {
        float lo, hi;
        unpack2(a0[q], lo, hi);
        h0[j][2 * q] = fmaxf(lo, 0.f); h0[j][2 * q + 1] = fmaxf(hi, 0.f);   // units 0..127
        unpack2(a1[q], lo, hi);
        m2[j][2 * q] = fmaxf(lo, 0.f); m2[j][2 * q + 1] = fmaxf(hi, 0.f);   // units 128..255
    }
    __syncthreads();

    // ------- MLP layer 1: 256 -> 256 -------
    const float2 mb1 = *reinterpret_cast<const float2*>(g_mb1c + 2 * j);
    {
        u64 m0 = pack2(mb1.x), m1 = pack2(mb1.y);
#pragma unroll
        for (int q = 0; q < NPAIR; ++q) { a0[q] = m0; a1[q] = m1; }
    }
    mlp_gemm(a0, a1, g_w1t,             h0, j);
    mlp_gemm(a0, a1, g_w1t + 128 * 256, m2, j);

#pragma unroll
    for (int q = 0; q < NPAIR; ++q) {
        float lo, hi;
        size_t gt = (size_t)(track0 + 2 * q);
        unpack2(a0[q], lo, hi);
        out[gt * HID + j]               = lo;
        out[(gt + 1) * HID + j]         = hi;
        unpack2(a1[q], lo, hi);
        out[gt * HID + 128 + j]         = lo;
        out[(gt + 1) * HID + 128 + j]   = hi;
    }
}

// ---------------- pos encoding ----------------
__global__ void pos_kernel(const float* __restrict__ tf, float* __restrict__ out)
{
    int idx = blockIdx.x * blockDim.x + threadIdx.x;
    if (idx >= NTRACK * 128) return;
    int gt = idx >> 7;
    int fi = idx & 127;
    int b = gt / NTRK, t = gt - b * NTRK;
    int coord = (fi < 64) ? 3 : 4;             // eta then phi
    float x = tf[((size_t)b * NFEAT + coord) * NTRK + t];
    int f = fi & 63;
    float p = x * g_posmul[f];
    float v = (f & 1) ? __cosf(p) : __sinf(p);
    out[(size_t)OUT_POS + (size_t)gt * 128 + fi] = v;
}

// ---------------- logpt / eta / phi passthrough ----------------
__global__ void scal_kernel(const float* __restrict__ tf, float* __restrict__ out)
{
    int gt = blockIdx.x * blockDim.x + threadIdx.x;
    if (gt >= NTRACK) return;
    int b = gt / NTRK, t = gt - b * NTRK;
    out[OUT_LOGPT + gt] = tf[((size_t)b * NFEAT + 2) * NTRK + t];
    out[OUT_ETA   + gt] = tf[((size_t)b * NFEAT + 3) * NTRK + t];
    out[OUT_PHI   + gt] = tf[((size_t)b * NFEAT + 4) * NTRK + t];
}

// ---------------- launch ----------------
extern "C" void kernel_launch(void* const* d_in, const int* in_sizes, int n_in,
                              void* d_out, int out_size)
{
    (void)in_sizes; (void)n_in; (void)out_size;
    const float* tf = (const float*)d_in[0];
    float* out = (float*)d_out;

    prep_kernel<<<256, 256>>>(
        (const float*)d_in[1], (const float*)d_in[2], (const float*)d_in[3], (const float*)d_in[4],
        (const float*)d_in[5], (const float*)d_in[6], (const float*)d_in[7], (const float*)d_in[8],
        (const float*)d_in[9], (const float*)d_in[10], (const float*)d_in[11], (const float*)d_in[12]);

    lstm_mlp_kernel<<<NTRACK / NT_TILE, CTA_THREADS>>>(tf, out);
    pos_kernel<<<(NTRACK * 128 + 255) / 256, 256>>>(tf, out);
    scal_kernel<<<(NTRACK + 255) / 256, 256>>>(tf, out);
}

// round 5
// speedup vs baseline: 1.0007x; 1.0007x over previous
#include <cuda_runtime.h>
#include <math.h>

#define NFEAT 18
#define NTRK  1500
#define BSZ   64
#define NTRACK (BSZ*NTRK)        // 96000
#define LHID  128
#define HID   256
#define TSTEPS 6
#define NT_TILE 16
#define NPAIR   8                // NT_TILE/2 f32x2 pairs
#define CTA_THREADS 128

// output layout offsets (floats)
#define OUT_POS   24576000       // 96000*256
#define OUT_LOGPT 36864000       // + 96000*128
#define OUT_ETA   36960000
#define OUT_PHI   37056000

typedef unsigned long long u64;

// ---------------- device scratch (transposed weights) ----------------
__device__ __align__(16) float g_wt_ih0[2   * 512];   // [k][j*4+g]
__device__ __align__(16) float g_wt_hh0[128 * 512];
__device__ __align__(16) float g_wt_ih1[128 * 512];
__device__ __align__(16) float g_wt_hh1[128 * 512];
__device__ __align__(16) float g_w0t  [131 * 256];    // [k][j*2+gg]
__device__ __align__(16) float g_w1t  [256 * 256];
__device__ __align__(16) float g_b0c  [512];          // [j*4+g] = b_ih+b_hh
__device__ __align__(16) float g_b1c  [512];
__device__ __align__(16) float g_mb0c [256];          // [j*2+gg]
__device__ __align__(16) float g_mb1c [256];
__device__ float g_posmul[64];                        // 2*pi / dim_t[f]

// ---------------- prep: transpose weights into k-major layouts ----------------
__global__ void prep_kernel(const float* __restrict__ W_ih0, const float* __restrict__ W_hh0,
                            const float* __restrict__ b_ih0, const float* __restrict__ b_hh0,
                            const float* __restrict__ W_ih1, const float* __restrict__ W_hh1,
                            const float* __restrict__ b_ih1, const float* __restrict__ b_hh1,
                            const float* __restrict__ mw0,   const float* __restrict__ mb0,
                            const float* __restrict__ mw1,   const float* __restrict__ mb1)
{
    int stride = gridDim.x * blockDim.x;
    int idx0 = blockIdx.x * blockDim.x + threadIdx.x;

    for (int i = idx0; i < 128 * 512; i += stride) {
        int k = i >> 9, r = i & 511, j = r >> 2, g = r & 3;
        int row = g * 128 + j;
        g_wt_hh0[i] = W_hh0[row * 128 + k];
        g_wt_ih1[i] = W_ih1[row * 128 + k];
        g_wt_hh1[i] = W_hh1[row * 128 + k];
    }
    for (int i = idx0; i < 2 * 512; i += stride) {
        int k = i >> 9, r = i & 511, j = r >> 2, g = r & 3;
        g_wt_ih0[i] = W_ih0[(g * 128 + j) * 2 + k];
    }
    for (int i = idx0; i < 131 * 256; i += stride) {
        int k = i >> 8, r = i & 255, j = r >> 1, gg = r & 1;
        g_w0t[i] = mw0[(gg * 128 + j) * 131 + k];
    }
    for (int i = idx0; i < 256 * 256; i += stride) {
        int k = i >> 8, r = i & 255, j = r >> 1, gg = r & 1;
        g_w1t[i] = mw1[(gg * 128 + j) * 256 + k];
    }
    for (int i = idx0; i < 512; i += stride) {
        int j = i >> 2, g = i & 3;
        g_b0c[i] = b_ih0[g * 128 + j] + b_hh0[g * 128 + j];
        g_b1c[i] = b_ih1[g * 128 + j] + b_hh1[g * 128 + j];
    }
    for (int i = idx0; i < 256; i += stride) {
        int j = i >> 1, gg = i & 1;
        g_mb0c[i] = mb0[gg * 128 + j];
        g_mb1c[i] = mb1[gg * 128 + j];
    }
    for (int i = idx0; i < 64; i += stride) {
        float e = (float)(2 * (i >> 1)) * (1.0f / 64.0f);
        g_posmul[i] = 6.283185307179586f / powf(10000.0f, e);
    }
}

// ---------------- f32x2 helpers ----------------
__device__ __forceinline__ u64 pack2(float x) {
    u64 r; asm("mov.b64 %0, {%1, %1};" : "=l"(r) : "f"(x)); return r;
}
__device__ __forceinline__ void unpack2(u64 v, float &lo, float &hi) {
    asm("mov.b64 {%0, %1}, %2;" : "=f"(lo), "=f"(hi) : "l"(v));
}
__device__ __forceinline__ void ffma2(u64 &d, u64 a, u64 b) {
    asm("fma.rn.f32x2 %0, %1, %2, %0;" : "+l"(d) : "l"(a), "l"(b));
}

// ---------------- activations ----------------
__device__ __forceinline__ float sigf(float x) { return 1.0f / (1.0f + __expf(-x)); }
__device__ __forceinline__ float tanh_fast(float x) {
    float ax = fabsf(x);
    float t = __expf(-2.0f * ax);
    float r = (1.0f - t) / (1.0f + t);
    return copysignf(r, x);
}

// ---------------- inner GEMM helpers (packed f32x2) ----------------
// acc[g][q] (pair n=2q,2q+1) += wt[k][4j+g] * hbuf[k][2q..2q+1], k = 0..127
__device__ __forceinline__ void gate_gemm(u64 acc[4][NPAIR],
                                          const float* __restrict__ wt,
                                          const float (&hbuf)[128][20], int j)
{
#pragma unroll 4
    for (int k = 0; k < 128; ++k) {
        float4 w = *reinterpret_cast<const float4*>(wt + k * 512 + 4 * j);
        u64 w0 = pack2(w.x), w1 = pack2(w.y), w2 = pack2(w.z), w3 = pack2(w.w);
#pragma unroll
        for (int q = 0; q < 4; ++q) {
            ulonglong2 hv = *reinterpret_cast<const ulonglong2*>(&hbuf[k][4 * q]);
            ffma2(acc[0][2 * q], w0, hv.x); ffma2(acc[0][2 * q + 1], w0, hv.y);
            ffma2(acc[1][2 * q], w1, hv.x); ffma2(acc[1][2 * q + 1], w1, hv.y);
            ffma2(acc[2][2 * q], w2, hv.x); ffma2(acc[2][2 * q + 1], w2, hv.y);
            ffma2(acc[3][2 * q], w3, hv.x); ffma2(acc[3][2 * q + 1], w3, hv.y);
        }
    }
}

// a0/a1[q] += wt[k][2j+gg] * hbuf[k][pair q], k = 0..127
__device__ __forceinline__ void mlp_gemm(u64 a0[NPAIR], u64 a1[NPAIR],
                                         const float* __restrict__ wt,
                                         const float (&hbuf)[128][20], int j)
{
#pragma unroll 4
    for (int k = 0; k < 128; ++k) {
        float2 w = *reinterpret_cast<const float2*>(wt + k * 256 + 2 * j);
        u64 w0 = pack2(w.x), w1 = pack2(w.y);
#pragma unroll
        for (int q = 0; q < 4; ++q) {
            ulonglong2 hv = *reinterpret_cast<const ulonglong2*>(&hbuf[k][4 * q]);
            ffma2(a0[2 * q], w0, hv.x); ffma2(a0[2 * q + 1], w0, hv.y);
            ffma2(a1[2 * q], w1, hv.x); ffma2(a1[2 * q + 1], w1, hv.y);
        }
    }
}

// ---------------- fused LSTM(2 layers, 6 steps) + MLP ----------------
__global__ void __launch_bounds__(CTA_THREADS, 3)
lstm_mlp_kernel(const float* __restrict__ tf, float* __restrict__ out)
{
    const int j = threadIdx.x;                 // hidden unit 0..127
    const int track0 = blockIdx.x * NT_TILE;

    __shared__ float h0[128][20];              // pad 20: 80B rows (16B multiple)
    __shared__ float h1[128][20];
    __shared__ float m2[128][20];
    __shared__ float xin[12][NT_TILE];         // feature-major: pairs contiguous in n
    __shared__ float f3s[3][NT_TILE];

    for (int i = j; i < 12 * NT_TILE; i += CTA_THREADS) {
        int f = i / NT_TILE, n = i % NT_TILE;
        int gt = track0 + n, b = gt / NTRK, t = gt - b * NTRK;
        xin[f][n] = tf[((size_t)b * NFEAT + 6 + f) * NTRK + t];
    }
    for (int i = j; i < 3 * NT_TILE; i += CTA_THREADS) {
        int f = i / NT_TILE, n = i % NT_TILE;
        int gt = track0 + n, b = gt / NTRK, t = gt - b * NTRK;
        f3s[f][n] = tf[((size_t)b * NFEAT + f) * NTRK + t];
    }

    float c0[NT_TILE], c1[NT_TILE];
#pragma unroll
    for (int n = 0; n < NT_TILE; ++n) { c0[n] = 0.f; c1[n] = 0.f; h0[j][n] = 0.f; h1[j][n] = 0.f; }
    __syncthreads();

    const float4 bias0 = *reinterpret_cast<const float4*>(g_b0c + 4 * j);
    const float4 bias1 = *reinterpret_cast<const float4*>(g_b1c + 4 * j);
    const u64 b0p[4] = { pack2(bias0.x), pack2(bias0.y), pack2(bias0.z), pack2(bias0.w) };
    const u64 b1p[4] = { pack2(bias1.x), pack2(bias1.y), pack2(bias1.z), pack2(bias1.w) };

    for (int t = 0; t < TSTEPS; ++t) {
        // ------- layer 0 -------
        u64 acc[4][NPAIR];
#pragma unroll
        for (int q = 0; q < NPAIR; ++q) {
            acc[0][q] = b0p[0]; acc[1][q] = b0p[1]; acc[2][q] = b0p[2]; acc[3][q] = b0p[3];
        }
#pragma unroll
        for (int k = 0; k < 2; ++k) {          // tiny input GEMM (x dim = 2)
            float4 w = *reinterpret_cast<const float4*>(g_wt_ih0 + k * 512 + 4 * j);
            u64 w0 = pack2(w.x), w1 = pack2(w.y), w2 = pack2(w.z), w3 = pack2(w.w);
#pragma unroll
            for (int q = 0; q < NPAIR; ++q) {
                u64 xv = *reinterpret_cast<const u64*>(&xin[2 * t + k][2 * q]);
                ffma2(acc[0][q], w0, xv);
                ffma2(acc[1][q], w1, xv);
                ffma2(acc[2][q], w2, xv);
                ffma2(acc[3][q], w3, xv);
            }
        }
        gate_gemm(acc, g_wt_hh0, h0, j);

        float hnew[NT_TILE];
#pragma unroll
        for (int q = 0; q < NPAIR; ++q) {
            float iv[2], fv[2], gv[2], ov[2];
            unpack2(acc[0][q], iv[0], iv[1]);
            unpack2(acc[1][q], fv[0], fv[1]);
            unpack2(acc[2][q], gv[0], gv[1]);
            unpack2(acc[3][q], ov[0], ov[1]);
#pragma unroll
            for (int u = 0; u < 2; ++u) {
                int n = 2 * q + u;
                float ii = sigf(iv[u]), ff = sigf(fv[u]);
                float gg = tanh_fast(gv[u]), oo = sigf(ov[u]);
                c0[n] = ff * c0[n] + ii * gg;
                hnew[n] = oo * tanh_fast(c0[n]);
            }
        }
        __syncthreads();
#pragma unroll
        for (int n = 0; n < NT_TILE; ++n) h0[j][n] = hnew[n];
        __syncthreads();

        // ------- layer 1 -------
#pragma unroll
        for (int q = 0; q < NPAIR; ++q) {
            acc[0][q] = b1p[0]; acc[1][q] = b1p[1]; acc[2][q] = b1p[2]; acc[3][q] = b1p[3];
        }
        gate_gemm(acc, g_wt_ih1, h0, j);
        gate_gemm(acc, g_wt_hh1, h1, j);
#pragma unroll
        for (int q = 0; q < NPAIR; ++q) {
            float iv[2], fv[2], gv[2], ov[2];
            unpack2(acc[0][q], iv[0], iv[1]);
            unpack2(acc[1][q], fv[0], fv[1]);
            unpack2(acc[2][q], gv[0], gv[1]);
            unpack2(acc[3][q], ov[0], ov[1]);
#pragma unroll
            for (int u = 0; u < 2; ++u) {
                int n = 2 * q + u;
                float ii = sigf(iv[u]), ff = sigf(fv[u]);
                float gg = tanh_fast(gv[u]), oo = sigf(ov[u]);
                c1[n] = ff * c1[n] + ii * gg;
                hnew[n] = oo * tanh_fast(c1[n]);
            }
        }
        __syncthreads();
#pragma unroll
        for (int n = 0; n < NT_TILE; ++n) h1[j][n] = hnew[n];
        __syncthreads();
    }

    // ------- MLP layer 0: (3 + 128) -> 256, ReLU -------
    u64 a0[NPAIR], a1[NPAIR];
    const float2 mb0 = *reinterpret_cast<const float2*>(g_mb0c + 2 * j);
    {
        u64 m0 = pack2(mb0.x), m1 = pack2(mb0.y);
#pragma unroll
        for (int q = 0; q < NPAIR; ++q) { a0[q] = m0; a1[q] = m1; }
    }
#pragma unroll
    for (int k = 0; k < 3; ++k) {
        float2 w = *reinterpret_cast<const float2*>(g_w0t + k * 256 + 2 * j);
        u64 w0 = pack2(w.x), w1 = pack2(w.y);
#pragma unroll
        for (int q = 0; q < NPAIR; ++q) {
            u64 xv = *reinterpret_cast<const u64*>(&f3s[k][2 * q]);
            ffma2(a0[q], w0, xv);
            ffma2(a1[q], w1, xv);
        }
    }
    mlp_gemm(a0, a1, g_w0t + 3 * 256, h1, j);
    // safe to overwrite h0/m2: all h0 reads finished before the last barrier
#pragma unroll
    for (int q = 0; q < NPAIR; ++q) {
        float lo, hi;
        unpack2(a0[q], lo, hi);
        h0[j][2 * q] = fmaxf(lo, 0.f); h0[j][2 * q + 1] = fmaxf(hi, 0.f);   // units 0..127
        unpack2(a1[q], lo, hi);
        m2[j][2 * q] = fmaxf(lo, 0.f); m2[j][2 * q + 1] = fmaxf(hi, 0.f);   // units 128..255
    }
    __syncthreads();

    // ------- MLP layer 1: 256 -> 256 -------
    const float2 mb1 = *reinterpret_cast<const float2*>(g_mb1c + 2 * j);
    {
        u64 m0 = pack2(mb1.x), m1 = pack2(mb1.y);
#pragma unroll
        for (int q = 0; q < NPAIR; ++q) { a0[q] = m0; a1[q] = m1; }
    }
    mlp_gemm(a0, a1, g_w1t,             h0, j);
    mlp_gemm(a0, a1, g_w1t + 128 * 256, m2, j);

#pragma unroll
    for (int q = 0; q < NPAIR; ++q) {
        float lo, hi;
        size_t gt = (size_t)(track0 + 2 * q);
        unpack2(a0[q], lo, hi);
        out[gt * HID + j]               = lo;
        out[(gt + 1) * HID + j]         = hi;
        unpack2(a1[q], lo, hi);
        out[gt * HID + 128 + j]         = lo;
        out[(gt + 1) * HID + 128 + j]   = hi;
    }
}

// ---------------- pos encoding ----------------
__global__ void pos_kernel(const float* __restrict__ tf, float* __restrict__ out)
{
    int idx = blockIdx.x * blockDim.x + threadIdx.x;
    if (idx >= NTRACK * 128) return;
    int gt = idx >> 7;
    int fi = idx & 127;
    int b = gt / NTRK, t = gt - b * NTRK;
    int coord = (fi < 64) ? 3 : 4;             // eta then phi
    float x = tf[((size_t)b * NFEAT + coord) * NTRK + t];
    int f = fi & 63;
    float p = x * g_posmul[f];
    float v = (f & 1) ? __cosf(p) : __sinf(p);
    out[(size_t)OUT_POS + (size_t)gt * 128 + fi] = v;
}

// ---------------- logpt / eta / phi passthrough ----------------
__global__ void scal_kernel(const float* __restrict__ tf, float* __restrict__ out)
{
    int gt = blockIdx.x * blockDim.x + threadIdx.x;
    if (gt >= NTRACK) return;
    int b = gt / NTRK, t = gt - b * NTRK;
    out[OUT_LOGPT + gt] = tf[((size_t)b * NFEAT + 2) * NTRK + t];
    out[OUT_ETA   + gt] = tf[((size_t)b * NFEAT + 3) * NTRK + t];
    out[OUT_PHI   + gt] = tf[((size_t)b * NFEAT + 4) * NTRK + t];
}

// ---------------- launch ----------------
extern "C" void kernel_launch(void* const* d_in, const int* in_sizes, int n_in,
                              void* d_out, int out_size)
{
    (void)in_sizes; (void)n_in; (void)out_size;
    const float* tf = (const float*)d_in[0];
    float* out = (float*)d_out;

    prep_kernel<<<256, 256>>>(
        (const float*)d_in[1], (const float*)d_in[2], (const float*)d_in[3], (const float*)d_in[4],
        (const float*)d_in[5], (const float*)d_in[6], (const float*)d_in[7], (const float*)d_in[8],
        (const float*)d_in[9], (const float*)d_in[10], (const float*)d_in[11], (const float*)d_in[12]);

    lstm_mlp_kernel<<<NTRACK / NT_TILE, CTA_THREADS>>>(tf, out);
    pos_kernel<<<(NTRACK * 128 + 255) / 256, 256>>>(tf, out);
    scal_kernel<<<(NTRACK + 255) / 256, 256>>>(tf, out);
}

// round 6
// speedup vs baseline: 5.5336x; 5.5297x over previous
#include <cuda_runtime.h>
#include <cuda_fp16.h>
#include <math.h>

#define NFEAT 18
#define NTRK  1500
#define BSZ   64
#define NTRACK (BSZ*NTRK)        // 96000
#define HID   256
#define TSTEPS 6
#define NT_TILE 32               // tracks per CTA
#define CTA_THREADS 256

// output layout offsets (floats)
#define OUT_POS   24576000       // 96000*256
#define OUT_LOGPT 36864000       // + 96000*128
#define OUT_ETA   36960000
#define OUT_PHI   37056000

typedef unsigned long long u64;
typedef unsigned int u32;

// ---------------- device scratch: fragment-packed fp16 weights ----------------
// layout: ((((w*MT + mt)*NKC + kc)*32 + lane)*4 + reg)*2 + dd   (halves)
__device__ __align__(16) __half P_hh0[65536];   // [8w][4g][8kc][32][4][2]
__device__ __align__(16) __half P_ih1[65536];
__device__ __align__(16) __half P_hh1[65536];
__device__ __align__(16) __half P_w0 [32768];   // [8w][2mt][8kc][32][4][2]
__device__ __align__(16) __half P_w1 [65536];   // [8w][2mt][16kc][32][4][2]
__device__ __align__(16) float g_b0c[512];      // b_ih0+b_hh0, row = g*128+unit
__device__ __align__(16) float g_b1c[512];
__device__ float g_posmul[64];

// ---------------- prep: pack weights into mma fragment order ----------------
__global__ void prep_kernel(const float* __restrict__ W_hh0,
                            const float* __restrict__ b_ih0, const float* __restrict__ b_hh0,
                            const float* __restrict__ W_ih1, const float* __restrict__ W_hh1,
                            const float* __restrict__ b_ih1, const float* __restrict__ b_hh1,
                            const float* __restrict__ mw0,   const float* __restrict__ mw1)
{
    int stride = gridDim.x * blockDim.x;
    int idx0 = blockIdx.x * blockDim.x + threadIdx.x;

    // LSTM hh0 / ih1 / hh1: M-tile = gate (4 per warp), K=128 (8 kc)
    for (int i = idx0; i < 65536; i += stride) {
        int dd = i & 1, reg = (i >> 1) & 3, lane = (i >> 3) & 31;
        int kc = (i >> 8) & 7, g = (i >> 11) & 3, w = (i >> 13) & 7;
        int row = g * 128 + w * 16 + (lane >> 2) + 8 * (reg & 1);
        int col = kc * 16 + (lane & 3) * 2 + dd + 8 * (reg >> 1);
        P_hh0[i] = __float2half_rn(W_hh0[row * 128 + col]);
        P_ih1[i] = __float2half_rn(W_ih1[row * 128 + col]);
        P_hh1[i] = __float2half_rn(W_hh1[row * 128 + col]);
    }
    // MLP0, K=128 part (cols 3..130 of mw0)
    for (int i = idx0; i < 32768; i += stride) {
        int dd = i & 1, reg = (i >> 1) & 3, lane = (i >> 3) & 31;
        int kc = (i >> 8) & 7, mt = (i >> 11) & 1, w = (i >> 12) & 7;
        int row = w * 32 + mt * 16 + (lane >> 2) + 8 * (reg & 1);
        int k   = kc * 16 + (lane & 3) * 2 + dd + 8 * (reg >> 1);
        P_w0[i] = __float2half_rn(mw0[row * 131 + 3 + k]);
    }
    // MLP1, K=256
    for (int i = idx0; i < 65536; i += stride) {
        int dd = i & 1, reg = (i >> 1) & 3, lane = (i >> 3) & 31;
        int kc = (i >> 8) & 15, mt = (i >> 12) & 1, w = (i >> 13) & 7;
        int row = w * 32 + mt * 16 + (lane >> 2) + 8 * (reg & 1);
        int k   = kc * 16 + (lane & 3) * 2 + dd + 8 * (reg >> 1);
        P_w1[i] = __float2half_rn(mw1[row * 256 + k]);
    }
    for (int i = idx0; i < 512; i += stride) {
        g_b0c[i] = b_ih0[i] + b_hh0[i];
        g_b1c[i] = b_ih1[i] + b_hh1[i];
    }
    for (int i = idx0; i < 64; i += stride) {
        float e = (float)(2 * (i >> 1)) * (1.0f / 64.0f);
        g_posmul[i] = 6.283185307179586f / powf(10000.0f, e);
    }
}

// ---------------- activations ----------------
__device__ __forceinline__ float sigf(float x) {
    return __fdividef(1.0f, 1.0f + __expf(-x));
}
__device__ __forceinline__ float tanh_fast(float x) {
    float ax = fabsf(x);
    float t = __expf(-2.0f * ax);
    float r = __fdividef(1.0f - t, 1.0f + t);
    return copysignf(r, x);
}

// ---------------- mma.sync wrapper ----------------
__device__ __forceinline__ void mma16816(float c[4], u32 a0, u32 a1, u32 a2, u32 a3,
                                         u32 b0, u32 b1) {
    asm("mma.sync.aligned.m16n8k16.row.col.f32.f16.f16.f32 "
        "{%0,%1,%2,%3}, {%4,%5,%6,%7}, {%8,%9}, {%0,%1,%2,%3};"
        : "+f"(c[0]), "+f"(c[1]), "+f"(c[2]), "+f"(c[3])
        : "r"(a0), "r"(a1), "r"(a2), "r"(a3), "r"(b0), "r"(b1));
}

// hB layout (half index): entry(kc, c, col) = 4 halves [kp0dd0, kp0dd1, kp1dd0, kp1dd1]
//   half_idx = ((kc*4 + c)*32 + col)*4 + kp*2 + dd,  unit u = kc*16 + 2c + dd + 8kp
__device__ __forceinline__ int hb_widx(int u, int n) {
    return ((u >> 4) * 4 + ((u & 7) >> 1)) * 128 + n * 4 + ((u >> 3) & 1) * 2 + (u & 1);
}

// fragment GEMM: acc[MT][4nt][4] += Wpacked * B(hB)
template<int MT, int NKC>
__device__ __forceinline__ void gemm_frag(float acc[][4][4],
                                          const __half* __restrict__ pw,
                                          const __half* __restrict__ hB, int lane)
{
    const int c = lane & 3, colr = lane >> 2;
#pragma unroll
    for (int kc = 0; kc < NKC; ++kc) {
        u64 bv[4];
#pragma unroll
        for (int nt = 0; nt < 4; ++nt)
            bv[nt] = *reinterpret_cast<const u64*>(hB + ((kc * 4 + c) * 32 + nt * 8 + colr) * 4);
#pragma unroll
        for (int mt = 0; mt < MT; ++mt) {
            uint4 a = *reinterpret_cast<const uint4*>(pw + ((mt * NKC + kc) * 32 + lane) * 8);
#pragma unroll
            for (int nt = 0; nt < 4; ++nt)
                mma16816(acc[mt][nt], a.x, a.y, a.z, a.w,
                         (u32)bv[nt], (u32)(bv[nt] >> 32));
        }
    }
}

// ---------------- fused LSTM + MLP (tensor-core) ----------------
__global__ void __launch_bounds__(CTA_THREADS, 2)
lstm_mlp_kernel(const float* __restrict__ tf,
                const float* __restrict__ W_ih0,   // [512][2] row-major
                const float* __restrict__ mw0,     // [256][131]
                const float* __restrict__ mb0,
                const float* __restrict__ mb1,
                float* __restrict__ out)
{
    const int tid  = threadIdx.x;
    const int lane = tid & 31;
    const int w    = tid >> 5;
    const int track0 = blockIdx.x * NT_TILE;
    const int lr = lane >> 2, c2 = (lane & 3) * 2;
    const int w16 = w * 16;

    __shared__ __align__(16) __half sh_h0[2 * 4096];   // double-buffered h0; reused as m2B
    __shared__ __align__(16) __half sh_h1[2 * 4096];
    __shared__ float sb0[512], sb1[512], swih0[1024];
    __shared__ float xin[12][NT_TILE], f3s[3][NT_TILE];

    // stage biases + W_ih0
    for (int i = tid; i < 512; i += CTA_THREADS) { sb0[i] = g_b0c[i]; sb1[i] = g_b1c[i]; }
    for (int i = tid; i < 1024; i += CTA_THREADS) swih0[i] = W_ih0[i];
    // stage per-track inputs
    for (int i = tid; i < 12 * NT_TILE; i += CTA_THREADS) {
        int f = i >> 5, n = i & 31;
        int gt = track0 + n, b = gt / NTRK, t = gt - b * NTRK;
        xin[f][n] = tf[((size_t)b * NFEAT + 6 + f) * NTRK + t];
    }
    for (int i = tid; i < 3 * NT_TILE; i += CTA_THREADS) {
        int f = i >> 5, n = i & 31;
        int gt = track0 + n, b = gt / NTRK, t = gt - b * NTRK;
        f3s[f][n] = tf[((size_t)b * NFEAT + f) * NTRK + t];
    }
    __syncthreads();

    float cst0[16], cst1[16];
#pragma unroll
    for (int i = 0; i < 16; ++i) { cst0[i] = 0.f; cst1[i] = 0.f; }

#pragma unroll 1
    for (int t = 0; t < TSTEPS; ++t) {
        const int cur = t & 1, prv = cur ^ 1;
        float acc[4][4][4];

        // ---------- layer 0: acc = bias + W_ih0 * x_t (+ W_hh0 * h0_prev) ----------
        {
            float bias8[4][2], wv[4][2][2];
#pragma unroll
            for (int g = 0; g < 4; ++g)
#pragma unroll
                for (int uu = 0; uu < 2; ++uu) {
                    int row = g * 128 + w16 + lr + 8 * uu;
                    bias8[g][uu] = sb0[row];
                    wv[g][uu][0] = swih0[row * 2 + 0];
                    wv[g][uu][1] = swih0[row * 2 + 1];
                }
            float xv[4][2][2];
#pragma unroll
            for (int nt = 0; nt < 4; ++nt)
#pragma unroll
                for (int dd = 0; dd < 2; ++dd) {
                    int n = nt * 8 + c2 + dd;
                    xv[nt][dd][0] = xin[2 * t + 0][n];
                    xv[nt][dd][1] = xin[2 * t + 1][n];
                }
#pragma unroll
            for (int g = 0; g < 4; ++g)
#pragma unroll
                for (int nt = 0; nt < 4; ++nt)
#pragma unroll
                    for (int uu = 0; uu < 2; ++uu)
#pragma unroll
                        for (int dd = 0; dd < 2; ++dd) {
                            float a = bias8[g][uu];
                            a = fmaf(wv[g][uu][0], xv[nt][dd][0], a);
                            a = fmaf(wv[g][uu][1], xv[nt][dd][1], a);
                            acc[g][nt][uu * 2 + dd] = a;
                        }
        }
        if (t > 0)
            gemm_frag<4, 8>(acc, P_hh0 + w * 8192, sh_h0 + prv * 4096, lane);

        // epilogue 0 -> h0[cur]
        {
            __half* hw = sh_h0 + cur * 4096;
#pragma unroll
            for (int nt = 0; nt < 4; ++nt)
#pragma unroll
                for (int idx = 0; idx < 4; ++idx) {
                    float iv = sigf(acc[0][nt][idx]);
                    float fv = sigf(acc[1][nt][idx]);
                    float gv = tanh_fast(acc[2][nt][idx]);
                    float ov = sigf(acc[3][nt][idx]);
                    float& cc = cst0[nt * 4 + idx];
                    cc = fv * cc + iv * gv;
                    float h = ov * tanh_fast(cc);
                    int u = w16 + lr + 8 * (idx >> 1);
                    int n = nt * 8 + c2 + (idx & 1);
                    hw[hb_widx(u, n)] = __float2half_rn(h);
                }
        }
        __syncthreads();

        // ---------- layer 1: acc = bias + W_ih1*h0[cur] (+ W_hh1*h1_prev) ----------
#pragma unroll
        for (int g = 0; g < 4; ++g)
#pragma unroll
            for (int uu = 0; uu < 2; ++uu) {
                float b = sb1[g * 128 + w16 + lr + 8 * uu];
#pragma unroll
                for (int nt = 0; nt < 4; ++nt) {
                    acc[g][nt][uu * 2 + 0] = b;
                    acc[g][nt][uu * 2 + 1] = b;
                }
            }
        gemm_frag<4, 8>(acc, P_ih1 + w * 8192, sh_h0 + cur * 4096, lane);
        if (t > 0)
            gemm_frag<4, 8>(acc, P_hh1 + w * 8192, sh_h1 + prv * 4096, lane);

        // epilogue 1 -> h1[cur]
        {
            __half* hw = sh_h1 + cur * 4096;
#pragma unroll
            for (int nt = 0; nt < 4; ++nt)
#pragma unroll
                for (int idx = 0; idx < 4; ++idx) {
                    float iv = sigf(acc[0][nt][idx]);
                    float fv = sigf(acc[1][nt][idx]);
                    float gv = tanh_fast(acc[2][nt][idx]);
                    float ov = sigf(acc[3][nt][idx]);
                    float& cc = cst1[nt * 4 + idx];
                    cc = fv * cc + iv * gv;
                    float h = ov * tanh_fast(cc);
                    int u = w16 + lr + 8 * (idx >> 1);
                    int n = nt * 8 + c2 + (idx & 1);
                    hw[hb_widx(u, n)] = __float2half_rn(h);
                }
        }
        __syncthreads();
    }

    const __half* hB1f = sh_h1 + ((TSTEPS - 1) & 1) * 4096;   // final h1

    // ---------- MLP layer 0: relu(b0 + W0[:,0:3]*f3 + W0[:,3:131]*h1) ----------
    {
        float macc[2][4][4];
#pragma unroll
        for (int mt = 0; mt < 2; ++mt)
#pragma unroll
            for (int du = 0; du < 2; ++du) {
                int row = w * 32 + mt * 16 + lr + 8 * du;
                float bv = mb0[row];
                float w0 = mw0[row * 131 + 0];
                float w1 = mw0[row * 131 + 1];
                float w2 = mw0[row * 131 + 2];
#pragma unroll
                for (int nt = 0; nt < 4; ++nt)
#pragma unroll
                    for (int dd = 0; dd < 2; ++dd) {
                        int n = nt * 8 + c2 + dd;
                        float a = bv;
                        a = fmaf(w0, f3s[0][n], a);
                        a = fmaf(w1, f3s[1][n], a);
                        a = fmaf(w2, f3s[2][n], a);
                        macc[mt][nt][du * 2 + dd] = a;
                    }
            }
        gemm_frag<2, 8>(macc, P_w0 + w * 4096, hB1f, lane);

        // relu -> m2B (overlays sh_h0, 256 units -> 8192 halves)
        __half* m2B = sh_h0;
#pragma unroll
        for (int mt = 0; mt < 2; ++mt)
#pragma unroll
            for (int nt = 0; nt < 4; ++nt)
#pragma unroll
                for (int idx = 0; idx < 4; ++idx) {
                    float v = fmaxf(macc[mt][nt][idx], 0.f);
                    int u = w * 32 + mt * 16 + lr + 8 * (idx >> 1);
                    int n = nt * 8 + c2 + (idx & 1);
                    m2B[hb_widx(u, n)] = __float2half_rn(v);
                }
    }
    __syncthreads();

    // ---------- MLP layer 1: out = b1 + W1 * m2 ----------
    {
        float oacc[2][4][4];
#pragma unroll
        for (int mt = 0; mt < 2; ++mt)
#pragma unroll
            for (int du = 0; du < 2; ++du) {
                float bv = mb1[w * 32 + mt * 16 + lr + 8 * du];
#pragma unroll
                for (int nt = 0; nt < 4; ++nt) {
                    oacc[mt][nt][du * 2 + 0] = bv;
                    oacc[mt][nt][du * 2 + 1] = bv;
                }
            }
        gemm_frag<2, 16>(oacc, P_w1 + w * 8192, sh_h0, lane);

#pragma unroll
        for (int mt = 0; mt < 2; ++mt)
#pragma unroll
            for (int nt = 0; nt < 4; ++nt)
#pragma unroll
                for (int idx = 0; idx < 4; ++idx) {
                    int row = w * 32 + mt * 16 + lr + 8 * (idx >> 1);
                    int n = nt * 8 + c2 + (idx & 1);
                    out[(size_t)(track0 + n) * HID + row] = oacc[mt][nt][idx];
                }
    }
}

// ---------------- pos encoding ----------------
__global__ void pos_kernel(const float* __restrict__ tf, float* __restrict__ out)
{
    int idx = blockIdx.x * blockDim.x + threadIdx.x;
    if (idx >= NTRACK * 128) return;
    int gt = idx >> 7;
    int fi = idx & 127;
    int b = gt / NTRK, t = gt - b * NTRK;
    int coord = (fi < 64) ? 3 : 4;             // eta then phi
    float x = tf[((size_t)b * NFEAT + coord) * NTRK + t];
    int f = fi & 63;
    float p = x * g_posmul[f];
    float v = (f & 1) ? __cosf(p) : __sinf(p);
    out[(size_t)OUT_POS + (size_t)gt * 128 + fi] = v;
}

// ---------------- logpt / eta / phi passthrough ----------------
__global__ void scal_kernel(const float* __restrict__ tf, float* __restrict__ out)
{
    int gt = blockIdx.x * blockDim.x + threadIdx.x;
    if (gt >= NTRACK) return;
    int b = gt / NTRK, t = gt - b * NTRK;
    out[OUT_LOGPT + gt] = tf[((size_t)b * NFEAT + 2) * NTRK + t];
    out[OUT_ETA   + gt] = tf[((size_t)b * NFEAT + 3) * NTRK + t];
    out[OUT_PHI   + gt] = tf[((size_t)b * NFEAT + 4) * NTRK + t];
}

// ---------------- launch ----------------
extern "C" void kernel_launch(void* const* d_in, const int* in_sizes, int n_in,
                              void* d_out, int out_size)
{
    (void)in_sizes; (void)n_in; (void)out_size;
    const float* tf = (const float*)d_in[0];
    float* out = (float*)d_out;

    prep_kernel<<<128, 256>>>(
        (const float*)d_in[2],                       // W_hh0
        (const float*)d_in[3], (const float*)d_in[4],// b_ih0, b_hh0
        (const float*)d_in[5], (const float*)d_in[6],// W_ih1, W_hh1
        (const float*)d_in[7], (const float*)d_in[8],// b_ih1, b_hh1
        (const float*)d_in[9], (const float*)d_in[11]// mlp_w0, mlp_w1
    );

    lstm_mlp_kernel<<<NTRACK / NT_TILE, CTA_THREADS>>>(
        tf,
        (const float*)d_in[1],     // W_ih0
        (const float*)d_in[9],     // mlp_w0 (first 3 cols)
        (const float*)d_in[10],    // mlp_b0
        (const float*)d_in[12],    // mlp_b1
        out);

    pos_kernel<<<(NTRACK * 128 + 255) / 256, 256>>>(tf, out);
    scal_kernel<<<(NTRACK + 255) / 256, 256>>>(tf, out);
}

// round 7
// speedup vs baseline: 5.9138x; 1.0687x over previous
#include <cuda_runtime.h>
#include <cuda_fp16.h>
#include <math.h>

#define NFEAT 18
#define NTRK  1500
#define BSZ   64
#define NTRACK (BSZ*NTRK)        // 96000
#define HID   256
#define TSTEPS 6
#define NT_TILE 32               // tracks per CTA
#define CTA_THREADS 256

// output layout offsets (floats)
#define OUT_POS   24576000       // 96000*256
#define OUT_LOGPT 36864000       // + 96000*128
#define OUT_ETA   36960000
#define OUT_PHI   37056000

typedef unsigned long long u64;
typedef unsigned int u32;

// ---------------- device scratch: fragment-packed fp16 weights ----------------
// layout: ((((w*MT + mt)*NKC + kc)*32 + lane)*4 + reg)*2 + dd   (halves)
__device__ __align__(16) __half P_hh0[65536];   // [8w][4g][8kc][32][4][2]
__device__ __align__(16) __half P_ih1[65536];
__device__ __align__(16) __half P_hh1[65536];
__device__ __align__(16) __half P_w0 [32768];   // [8w][2mt][8kc][32][4][2]
__device__ __align__(16) __half P_w1 [65536];   // [8w][2mt][16kc][32][4][2]
__device__ __align__(16) float g_b0c[512];      // b_ih0+b_hh0, row = g*128+unit
__device__ __align__(16) float g_b1c[512];
__device__ float g_posmul[64];

// ---------------- prep: pack weights into mma fragment order ----------------
__global__ void prep_kernel(const float* __restrict__ W_hh0,
                            const float* __restrict__ b_ih0, const float* __restrict__ b_hh0,
                            const float* __restrict__ W_ih1, const float* __restrict__ W_hh1,
                            const float* __restrict__ b_ih1, const float* __restrict__ b_hh1,
                            const float* __restrict__ mw0,   const float* __restrict__ mw1)
{
    int stride = gridDim.x * blockDim.x;
    int idx0 = blockIdx.x * blockDim.x + threadIdx.x;

    // LSTM hh0 / ih1 / hh1: M-tile = gate (4 per warp), K=128 (8 kc)
    for (int i = idx0; i < 65536; i += stride) {
        int dd = i & 1, reg = (i >> 1) & 3, lane = (i >> 3) & 31;
        int kc = (i >> 8) & 7, g = (i >> 11) & 3, w = (i >> 13) & 7;
        int row = g * 128 + w * 16 + (lane >> 2) + 8 * (reg & 1);
        int col = kc * 16 + (lane & 3) * 2 + dd + 8 * (reg >> 1);
        P_hh0[i] = __float2half_rn(W_hh0[row * 128 + col]);
        P_ih1[i] = __float2half_rn(W_ih1[row * 128 + col]);
        P_hh1[i] = __float2half_rn(W_hh1[row * 128 + col]);
    }
    // MLP0, K=128 part (cols 3..130 of mw0)
    for (int i = idx0; i < 32768; i += stride) {
        int dd = i & 1, reg = (i >> 1) & 3, lane = (i >> 3) & 31;
        int kc = (i >> 8) & 7, mt = (i >> 11) & 1, w = (i >> 12) & 7;
        int row = w * 32 + mt * 16 + (lane >> 2) + 8 * (reg & 1);
        int k   = kc * 16 + (lane & 3) * 2 + dd + 8 * (reg >> 1);
        P_w0[i] = __float2half_rn(mw0[row * 131 + 3 + k]);
    }
    // MLP1, K=256
    for (int i = idx0; i < 65536; i += stride) {
        int dd = i & 1, reg = (i >> 1) & 3, lane = (i >> 3) & 31;
        int kc = (i >> 8) & 15, mt = (i >> 12) & 1, w = (i >> 13) & 7;
        int row = w * 32 + mt * 16 + (lane >> 2) + 8 * (reg & 1);
        int k   = kc * 16 + (lane & 3) * 2 + dd + 8 * (reg >> 1);
        P_w1[i] = __float2half_rn(mw1[row * 256 + k]);
    }
    for (int i = idx0; i < 512; i += stride) {
        g_b0c[i] = b_ih0[i] + b_hh0[i];
        g_b1c[i] = b_ih1[i] + b_hh1[i];
    }
    for (int i = idx0; i < 64; i += stride) {
        float e = (float)(2 * (i >> 1)) * (1.0f / 64.0f);
        g_posmul[i] = 6.283185307179586f / powf(10000.0f, e);
    }
}

// ---------------- activations (MUFU.TANH based) ----------------
__device__ __forceinline__ float tanh_mufu(float x) {
    float r; asm("tanh.approx.f32 %0, %1;" : "=f"(r) : "f"(x)); return r;
}
__device__ __forceinline__ float sigf(float x) {
    return fmaf(tanh_mufu(0.5f * x), 0.5f, 0.5f);
}

// ---------------- mma.sync wrapper ----------------
__device__ __forceinline__ void mma16816(float c[4], u32 a0, u32 a1, u32 a2, u32 a3,
                                         u32 b0, u32 b1) {
    asm("mma.sync.aligned.m16n8k16.row.col.f32.f16.f16.f32 "
        "{%0,%1,%2,%3}, {%4,%5,%6,%7}, {%8,%9}, {%0,%1,%2,%3};"
        : "+f"(c[0]), "+f"(c[1]), "+f"(c[2]), "+f"(c[3])
        : "r"(a0), "r"(a1), "r"(a2), "r"(a3), "r"(b0), "r"(b1));
}

// hB layout (half index): entry(kc, c, col) = 4 halves [kp0dd0, kp0dd1, kp1dd0, kp1dd1]
//   half_idx = ((kc*4 + c)*32 + col)*4 + kp*2 + dd,  unit u = kc*16 + 2c + dd + 8kp
__device__ __forceinline__ int hb_widx(int u, int n) {
    return ((u >> 4) * 4 + ((u & 7) >> 1)) * 128 + n * 4 + ((u >> 3) & 1) * 2 + (u & 1);
}

// fragment GEMM: acc[MT][4nt][4] += Wpacked * B(hB)
template<int MT, int NKC>
__device__ __forceinline__ void gemm_frag(float acc[][4][4],
                                          const __half* __restrict__ pw,
                                          const __half* __restrict__ hB, int lane)
{
    const int c = lane & 3, colr = lane >> 2;
#pragma unroll
    for (int kc = 0; kc < NKC; ++kc) {
        u64 bv[4];
#pragma unroll
        for (int nt = 0; nt < 4; ++nt)
            bv[nt] = *reinterpret_cast<const u64*>(hB + ((kc * 4 + c) * 32 + nt * 8 + colr) * 4);
#pragma unroll
        for (int mt = 0; mt < MT; ++mt) {
            uint4 a = *reinterpret_cast<const uint4*>(pw + ((mt * NKC + kc) * 32 + lane) * 8);
#pragma unroll
            for (int nt = 0; nt < 4; ++nt)
                mma16816(acc[mt][nt], a.x, a.y, a.z, a.w,
                         (u32)bv[nt], (u32)(bv[nt] >> 32));
        }
    }
}

// ---------------- fused LSTM + MLP (tensor-core) ----------------
__global__ void __launch_bounds__(CTA_THREADS, 2)
lstm_mlp_kernel(const float* __restrict__ tf,
                const float* __restrict__ W_ih0,   // [512][2] row-major
                const float* __restrict__ mw0,     // [256][131]
                const float* __restrict__ mb0,
                const float* __restrict__ mb1,
                float* __restrict__ out)
{
    const int tid  = threadIdx.x;
    const int lane = tid & 31;
    const int w    = tid >> 5;
    const int track0 = blockIdx.x * NT_TILE;
    const int lr = lane >> 2, c2 = (lane & 3) * 2;
    const int w16 = w * 16;

    __shared__ __align__(16) __half sh_h0[2 * 4096];   // double-buffered h0; reused as m2B
    __shared__ __align__(16) __half sh_h1[2 * 4096];
    __shared__ float sb0[512], sb1[512], swih0[1024];
    __shared__ float xin[12][NT_TILE], f3s[3][NT_TILE];

    // stage biases + W_ih0
    for (int i = tid; i < 512; i += CTA_THREADS) { sb0[i] = g_b0c[i]; sb1[i] = g_b1c[i]; }
    for (int i = tid; i < 1024; i += CTA_THREADS) swih0[i] = W_ih0[i];
    // stage per-track inputs
    for (int i = tid; i < 12 * NT_TILE; i += CTA_THREADS) {
        int f = i >> 5, n = i & 31;
        int gt = track0 + n, b = gt / NTRK, t = gt - b * NTRK;
        xin[f][n] = tf[((size_t)b * NFEAT + 6 + f) * NTRK + t];
    }
    for (int i = tid; i < 3 * NT_TILE; i += CTA_THREADS) {
        int f = i >> 5, n = i & 31;
        int gt = track0 + n, b = gt / NTRK, t = gt - b * NTRK;
        f3s[f][n] = tf[((size_t)b * NFEAT + f) * NTRK + t];
    }
    __syncthreads();

    float cst0[16], cst1[16];
#pragma unroll
    for (int i = 0; i < 16; ++i) { cst0[i] = 0.f; cst1[i] = 0.f; }

#pragma unroll 1
    for (int t = 0; t < TSTEPS; ++t) {
        const int cur = t & 1, prv = cur ^ 1;
        float acc[4][4][4];

        // ---------- layer 0: acc = bias + W_ih0 * x_t (+ W_hh0 * h0_prev) ----------
        {
            float bias8[4][2], wv[4][2][2];
#pragma unroll
            for (int g = 0; g < 4; ++g)
#pragma unroll
                for (int uu = 0; uu < 2; ++uu) {
                    int row = g * 128 + w16 + lr + 8 * uu;
                    bias8[g][uu] = sb0[row];
                    wv[g][uu][0] = swih0[row * 2 + 0];
                    wv[g][uu][1] = swih0[row * 2 + 1];
                }
            float xv[4][2][2];
#pragma unroll
            for (int nt = 0; nt < 4; ++nt)
#pragma unroll
                for (int dd = 0; dd < 2; ++dd) {
                    int n = nt * 8 + c2 + dd;
                    xv[nt][dd][0] = xin[2 * t + 0][n];
                    xv[nt][dd][1] = xin[2 * t + 1][n];
                }
#pragma unroll
            for (int g = 0; g < 4; ++g)
#pragma unroll
                for (int nt = 0; nt < 4; ++nt)
#pragma unroll
                    for (int uu = 0; uu < 2; ++uu)
#pragma unroll
                        for (int dd = 0; dd < 2; ++dd) {
                            float a = bias8[g][uu];
                            a = fmaf(wv[g][uu][0], xv[nt][dd][0], a);
                            a = fmaf(wv[g][uu][1], xv[nt][dd][1], a);
                            acc[g][nt][uu * 2 + dd] = a;
                        }
        }
        if (t > 0)
            gemm_frag<4, 8>(acc, P_hh0 + w * 8192, sh_h0 + prv * 4096, lane);

        // epilogue 0 -> h0[cur]
        {
            __half* hw = sh_h0 + cur * 4096;
#pragma unroll
            for (int nt = 0; nt < 4; ++nt)
#pragma unroll
                for (int idx = 0; idx < 4; ++idx) {
                    float iv = sigf(acc[0][nt][idx]);
                    float fv = sigf(acc[1][nt][idx]);
                    float gv = tanh_mufu(acc[2][nt][idx]);
                    float ov = sigf(acc[3][nt][idx]);
                    float& cc = cst0[nt * 4 + idx];
                    cc = fv * cc + iv * gv;
                    float h = ov * tanh_mufu(cc);
                    int u = w16 + lr + 8 * (idx >> 1);
                    int n = nt * 8 + c2 + (idx & 1);
                    hw[hb_widx(u, n)] = __float2half_rn(h);
                }
        }
        __syncthreads();

        // ---------- layer 1: acc = bias + W_ih1*h0[cur] (+ W_hh1*h1_prev) ----------
#pragma unroll
        for (int g = 0; g < 4; ++g)
#pragma unroll
            for (int uu = 0; uu < 2; ++uu) {
                float b = sb1[g * 128 + w16 + lr + 8 * uu];
#pragma unroll
                for (int nt = 0; nt < 4; ++nt) {
                    acc[g][nt][uu * 2 + 0] = b;
                    acc[g][nt][uu * 2 + 1] = b;
                }
            }
        gemm_frag<4, 8>(acc, P_ih1 + w * 8192, sh_h0 + cur * 4096, lane);
        if (t > 0)
            gemm_frag<4, 8>(acc, P_hh1 + w * 8192, sh_h1 + prv * 4096, lane);

        // epilogue 1 -> h1[cur]
        {
            __half* hw = sh_h1 + cur * 4096;
#pragma unroll
            for (int nt = 0; nt < 4; ++nt)
#pragma unroll
                for (int idx = 0; idx < 4; ++idx) {
                    float iv = sigf(acc[0][nt][idx]);
                    float fv = sigf(acc[1][nt][idx]);
                    float gv = tanh_mufu(acc[2][nt][idx]);
                    float ov = sigf(acc[3][nt][idx]);
                    float& cc = cst1[nt * 4 + idx];
                    cc = fv * cc + iv * gv;
                    float h = ov * tanh_mufu(cc);
                    int u = w16 + lr + 8 * (idx >> 1);
                    int n = nt * 8 + c2 + (idx & 1);
                    hw[hb_widx(u, n)] = __float2half_rn(h);
                }
        }
        __syncthreads();
    }

    const __half* hB1f = sh_h1 + ((TSTEPS - 1) & 1) * 4096;   // final h1

    // ---------- MLP layer 0: relu(b0 + W0[:,0:3]*f3 + W0[:,3:131]*h1) ----------
    {
        float macc[2][4][4];
#pragma unroll
        for (int mt = 0; mt < 2; ++mt)
#pragma unroll
            for (int du = 0; du < 2; ++du) {
                int row = w * 32 + mt * 16 + lr + 8 * du;
                float bv = mb0[row];
                float w0 = mw0[row * 131 + 0];
                float w1 = mw0[row * 131 + 1];
                float w2 = mw0[row * 131 + 2];
#pragma unroll
                for (int nt = 0; nt < 4; ++nt)
#pragma unroll
                    for (int dd = 0; dd < 2; ++dd) {
                        int n = nt * 8 + c2 + dd;
                        float a = bv;
                        a = fmaf(w0, f3s[0][n], a);
                        a = fmaf(w1, f3s[1][n], a);
                        a = fmaf(w2, f3s[2][n], a);
                        macc[mt][nt][du * 2 + dd] = a;
                    }
            }
        gemm_frag<2, 8>(macc, P_w0 + w * 4096, hB1f, lane);

        // relu -> m2B (overlays sh_h0, 256 units -> 8192 halves)
        __half* m2B = sh_h0;
#pragma unroll
        for (int mt = 0; mt < 2; ++mt)
#pragma unroll
            for (int nt = 0; nt < 4; ++nt)
#pragma unroll
                for (int idx = 0; idx < 4; ++idx) {
                    float v = fmaxf(macc[mt][nt][idx], 0.f);
                    int u = w * 32 + mt * 16 + lr + 8 * (idx >> 1);
                    int n = nt * 8 + c2 + (idx & 1);
                    m2B[hb_widx(u, n)] = __float2half_rn(v);
                }
    }
    __syncthreads();

    // ---------- MLP layer 1: out = b1 + W1 * m2 ----------
    {
        float oacc[2][4][4];
#pragma unroll
        for (int mt = 0; mt < 2; ++mt)
#pragma unroll
            for (int du = 0; du < 2; ++du) {
                float bv = mb1[w * 32 + mt * 16 + lr + 8 * du];
#pragma unroll
                for (int nt = 0; nt < 4; ++nt) {
                    oacc[mt][nt][du * 2 + 0] = bv;
                    oacc[mt][nt][du * 2 + 1] = bv;
                }
            }
        gemm_frag<2, 16>(oacc, P_w1 + w * 8192, sh_h0, lane);

#pragma unroll
        for (int mt = 0; mt < 2; ++mt)
#pragma unroll
            for (int nt = 0; nt < 4; ++nt)
#pragma unroll
                for (int idx = 0; idx < 4; ++idx) {
                    int row = w * 32 + mt * 16 + lr + 8 * (idx >> 1);
                    int n = nt * 8 + c2 + (idx & 1);
                    out[(size_t)(track0 + n) * HID + row] = oacc[mt][nt][idx];
                }
    }
}

// ---------------- pos encoding ----------------
__global__ void pos_kernel(const float* __restrict__ tf, float* __restrict__ out)
{
    int idx = blockIdx.x * blockDim.x + threadIdx.x;
    if (idx >= NTRACK * 128) return;
    int gt = idx >> 7;
    int fi = idx & 127;
    int b = gt / NTRK, t = gt - b * NTRK;
    int coord = (fi < 64) ? 3 : 4;             // eta then phi
    float x = tf[((size_t)b * NFEAT + coord) * NTRK + t];
    int f = fi & 63;
    float p = x * g_posmul[f];
    float v = (f & 1) ? __cosf(p) : __sinf(p);
    out[(size_t)OUT_POS + (size_t)gt * 128 + fi] = v;
}

// ---------------- logpt / eta / phi passthrough ----------------
__global__ void scal_kernel(const float* __restrict__ tf, float* __restrict__ out)
{
    int gt = blockIdx.x * blockDim.x + threadIdx.x;
    if (gt >= NTRACK) return;
    int b = gt / NTRK, t = gt - b * NTRK;
    out[OUT_LOGPT + gt] = tf[((size_t)b * NFEAT + 2) * NTRK + t];
    out[OUT_ETA   + gt] = tf[((size_t)b * NFEAT + 3) * NTRK + t];
    out[OUT_PHI   + gt] = tf[((size_t)b * NFEAT + 4) * NTRK + t];
}

// ---------------- launch ----------------
extern "C" void kernel_launch(void* const* d_in, const int* in_sizes, int n_in,
                              void* d_out, int out_size)
{
    (void)in_sizes; (void)n_in; (void)out_size;
    const float* tf = (const float*)d_in[0];
    float* out = (float*)d_out;

    prep_kernel<<<128, 256>>>(
        (const float*)d_in[2],                       // W_hh0
        (const float*)d_in[3], (const float*)d_in[4],// b_ih0, b_hh0
        (const float*)d_in[5], (const float*)d_in[6],// W_ih1, W_hh1
        (const float*)d_in[7], (const float*)d_in[8],// b_ih1, b_hh1
        (const float*)d_in[9], (const float*)d_in[11]// mlp_w0, mlp_w1
    );

    lstm_mlp_kernel<<<NTRACK / NT_TILE, CTA_THREADS>>>(
        tf,
        (const float*)d_in[1],     // W_ih0
        (const float*)d_in[9],     // mlp_w0 (first 3 cols)
        (const float*)d_in[10],    // mlp_b0
        (const float*)d_in[12],    // mlp_b1
        out);

    pos_kernel<<<(NTRACK * 128 + 255) / 256, 256>>>(tf, out);
    scal_kernel<<<(NTRACK + 255) / 256, 256>>>(tf, out);
}